// round 13
// baseline (speedup 1.0000x reference)
#include <cuda_runtime.h>
#include <cuda_bf16.h>
#include <cstdint>

#define D    64
#define H1   128
#define H2   64
#define NMAX 1024
#define EPS_F 1e-10f
#define THRESH 2e-3f
#define FIXCAP (1 << 20)

// Scratch (no allocations allowed)
__device__ float g_A[NMAX * H1];        // X @ W1[:D] + b1
__device__ float g_B[NMAX * H1];        // X @ W1[D:]
__device__ float g_L[NMAX * NMAX];      // logit diff per ordered pair
__device__ uint4 g_W2q[64 * 32];        // W2 bf16 splits packed as B-frag quads
__device__ unsigned int g_fixlist[FIXCAP];
__device__ int g_fixcnt;

// ---------------------------------------------------------------------------
// Kernel 1: A[i,k], B[i,k]. 2 rows per block, 256 threads (grid 512).
// ---------------------------------------------------------------------------
__global__ void ab_kernel(const float* __restrict__ X,
                          const float* __restrict__ W1,
                          const float* __restrict__ b1)
{
    __shared__ float xs[2][D];
    const int i0 = blockIdx.x * 2;
    const int tid = threadIdx.x;
    const int r = tid >> 7;              // row 0/1
    const int k = tid & 127;

    if (tid < 128) xs[tid >> 6][tid & 63] = X[i0 * D + tid];
    __syncthreads();

    float a = b1[k];
    float b = 0.0f;
#pragma unroll
    for (int d = 0; d < D; d++) {
        const float x = xs[r][d];
        a = fmaf(x, W1[d * H1 + k], a);
        b = fmaf(x, W1[(D + d) * H1 + k], b);
    }
    g_A[(i0 + r) * H1 + k] = a;
    g_B[(i0 + r) * H1 + k] = b;
}

// ---------------------------------------------------------------------------
// Kernel 1b: split W2 into bf16 hi/mid, pack into B-fragment quads.
// quad[n][ks*4+t] = {b0hi, b0mid, b1hi, b1mid} where b0 covers k = 16ks+2t,+1
// and b1 covers k = 16ks+2t+8,+9 (each word = {lo: k even, hi: k odd}).
// Also resets the fixup counter.
// ---------------------------------------------------------------------------
__global__ void w2prep_kernel(const float* __restrict__ W2)
{
    const int idx = blockIdx.x * 256 + threadIdx.x;   // 0..4095
    if (idx == 0) g_fixcnt = 0;
    const int nn = idx >> 6;       // output col n (0..63)
    const int kk = idx & 63;       // k-pair index (0..63)
    const float w0 = W2[(2 * kk) * H2 + nn];
    const float w1 = W2[(2 * kk + 1) * H2 + nn];
    unsigned hiw, midw;
    asm("cvt.rn.satfinite.bf16x2.f32 %0, %1, %2;" : "=r"(hiw) : "f"(w1), "f"(w0));
    const float r0 = w0 - __uint_as_float(hiw << 16);
    const float r1 = w1 - __uint_as_float(hiw & 0xffff0000u);
    asm("cvt.rn.satfinite.bf16x2.f32 %0, %1, %2;" : "=r"(midw) : "f"(r1), "f"(r0));
    const int ks = kk >> 3;
    const int gg = kk & 7;
    const int t = gg & 3;
    const int half = gg >> 2;     // 0 -> b0 words, 1 -> b1 words
    ((uint2*)g_W2q)[(nn * 32 + ks * 4 + t) * 2 + half] = make_uint2(hiw, midw);
}

// ---------------------------------------------------------------------------
// Kernel 2: HMMA pair MLP. CTA = 512 thr (16 warps), tile = 16 i x 64 j
// (4 sub-tiles of 16x16). Warp w covers the single i-row i0 + w.
// 3 bf16 split products (hi*hi + hi*mid + mid*hi) -> fp32-accurate to ~1e-4.
// Natural register footprint ~90 regs -> 4 warps/SMSP without spills.
// ---------------------------------------------------------------------------
#define SB_STRIDE 136                    // floats; (136*g+2t)%32 conflict-free
#define WQ_STRIDE 36                     // uint4;  (4g+t)%8 distinct per phase
#define SM_AS_OFF 0                      // 16*128 floats
#define SM_BS_OFF (16 * 128)             // 16*136 floats
#define SM_WQ_B   ((SM_BS_OFF + 16 * SB_STRIDE) * 4)   // byte offset, 16B-aligned
#define SM_B2_B   (SM_WQ_B + 64 * WQ_STRIDE * 16)
#define SM_W3_B   (SM_B2_B + 256)
#define SMEM_BYTES (SM_W3_B + 256)

__device__ __forceinline__ void mma_bf16(float* c, const unsigned* a,
                                         unsigned b0, unsigned b1)
{
    asm("mma.sync.aligned.m16n8k16.row.col.f32.bf16.bf16.f32 "
        "{%0,%1,%2,%3}, {%4,%5,%6,%7}, {%8,%9}, {%0,%1,%2,%3};"
        : "+f"(c[0]), "+f"(c[1]), "+f"(c[2]), "+f"(c[3])
        : "r"(a[0]), "r"(a[1]), "r"(a[2]), "r"(a[3]), "r"(b0), "r"(b1));
}

__device__ __forceinline__ void hsplit(float2 a, float2 b,
                                       unsigned& hi, unsigned& mid)
{
    const float h0 = fmaxf(a.x + b.x, 0.0f);
    const float h1 = fmaxf(a.y + b.y, 0.0f);
    asm("cvt.rn.satfinite.bf16x2.f32 %0, %1, %2;" : "=r"(hi) : "f"(h1), "f"(h0));
    const float r0 = h0 - __uint_as_float(hi << 16);
    const float r1 = h1 - __uint_as_float(hi & 0xffff0000u);
    asm("cvt.rn.satfinite.bf16x2.f32 %0, %1, %2;" : "=r"(mid) : "f"(r1), "f"(r0));
}

__global__ __launch_bounds__(512, 1)
void pair_mma_kernel(const float* __restrict__ b2,
                     const float* __restrict__ W3,
                     const float* __restrict__ b3,
                     int n)
{
    extern __shared__ unsigned char smraw[];
    float* As  = (float*)smraw;                     // [16][128]
    float* Bs  = (float*)smraw + SM_BS_OFF;         // [16][136]
    uint4* W2q = (uint4*)(smraw + SM_WQ_B);         // [64][36]
    float* b2s = (float*)(smraw + SM_B2_B);         // [64]
    float* w3s = (float*)(smraw + SM_W3_B);         // [64]

    const int tid = threadIdx.x;
    const int w = tid >> 5;        // 0..15 : i-row within tile
    const int l = tid & 31;
    const int g = l >> 2;          // groupID 0..7
    const int t = l & 3;

    const int i0 = blockIdx.y * 16;

    // ---- stage As (16x128 fp32) and W2 quads (64x32 uint4), b2/w3 ----
    {
        const float4* srcA = (const float4*)g_A;
        {
            const int e = tid;                   // 0..511 float4s
            const int r = e >> 5, c4 = e & 31;
            *(float4*)&As[r * 128 + c4 * 4] = srcA[(i0 + r) * 32 + c4];
        }
#pragma unroll
        for (int q = 0; q < 4; q++) {
            const int e = tid + q * 512;         // 0..2047
            const int nn = e >> 5, c = e & 31;
            W2q[nn * WQ_STRIDE + c] = g_W2q[nn * 32 + c];
        }
        if (tid < 64) {
            b2s[tid] = b2[tid];
            w3s[tid] = W3[tid * 2 + 1] - W3[tid * 2];
        }
    }
    const float b3d = __ldg(&b3[1]) - __ldg(&b3[0]);

    for (int tt = 0; tt < 4; tt++) {
        const int j0 = (blockIdx.x * 4 + tt) * 16;
        __syncthreads();   // protect Bs (and cover prologue on tt=0)
        {
            const float2* srcB = (const float2*)g_B;
#pragma unroll
            for (int q = 0; q < 2; q++) {
                const int e = tid + q * 512;     // 0..1023 float2s
                const int r = e >> 6, c2 = e & 63;
                *(float2*)&Bs[r * SB_STRIDE + c2 * 2] = srcB[(j0 + r) * 64 + c2];
            }
        }
        __syncthreads();

        float acc[8][4];
#pragma unroll
        for (int nb = 0; nb < 8; nb++)
#pragma unroll
            for (int c = 0; c < 4; c++) acc[nb][c] = 0.0f;

#pragma unroll
        for (int ks = 0; ks < 8; ks++) {
            const int k0 = ks * 16;
            const float2 blo_g  = *(const float2*)&Bs[g * SB_STRIDE + k0 + 2 * t];
            const float2 bhi_g  = *(const float2*)&Bs[g * SB_STRIDE + k0 + 2 * t + 8];
            const float2 blo_g8 = *(const float2*)&Bs[(g + 8) * SB_STRIDE + k0 + 2 * t];
            const float2 bhi_g8 = *(const float2*)&Bs[(g + 8) * SB_STRIDE + k0 + 2 * t + 8];

            unsigned ahi[4], amid[4];
            {
                const float2 alo = *(const float2*)&As[w * 128 + k0 + 2 * t];
                const float2 ah2 = *(const float2*)&As[w * 128 + k0 + 2 * t + 8];
                hsplit(alo, blo_g,  ahi[0], amid[0]);  // row g
                hsplit(alo, blo_g8, ahi[1], amid[1]);  // row g+8
                hsplit(ah2, bhi_g,  ahi[2], amid[2]);  // row g,  k+8
                hsplit(ah2, bhi_g8, ahi[3], amid[3]);  // row g+8,k+8
            }

            // Four 2-nb batches: 2 quads live, product-major within each
            // batch -> 2 independent MMAs between accumulator reuses; 4
            // warps/SMSP supply cross-warp overlap on top.
#pragma unroll
            for (int qb = 0; qb < 4; qb++) {
                uint4 q[2];
#pragma unroll
                for (int nq = 0; nq < 2; nq++)
                    q[nq] = W2q[((qb * 2 + nq) * 8 + g) * WQ_STRIDE + ks * 4 + t];
#pragma unroll
                for (int nq = 0; nq < 2; nq++)             // hi*hi
                    mma_bf16(acc[qb * 2 + nq], ahi,  q[nq].x, q[nq].z);
#pragma unroll
                for (int nq = 0; nq < 2; nq++)             // hi*mid
                    mma_bf16(acc[qb * 2 + nq], ahi,  q[nq].y, q[nq].w);
#pragma unroll
                for (int nq = 0; nq < 2; nq++)             // mid*hi
                    mma_bf16(acc[qb * 2 + nq], amid, q[nq].x, q[nq].z);
            }
        }

        // ---- epilogue: +b2, relu, dot w3diff, reduce over 4 lanes ----
        float s[2] = {0.f, 0.f};
#pragma unroll
        for (int nb = 0; nb < 8; nb++) {
            const float2 bb = *(const float2*)&b2s[nb * 8 + 2 * t];
            const float2 ww = *(const float2*)&w3s[nb * 8 + 2 * t];
            s[0] += fmaxf(acc[nb][0] + bb.x, 0.f) * ww.x
                  + fmaxf(acc[nb][1] + bb.y, 0.f) * ww.y;
            s[1] += fmaxf(acc[nb][2] + bb.x, 0.f) * ww.x
                  + fmaxf(acc[nb][3] + bb.y, 0.f) * ww.y;
        }
#pragma unroll
        for (int r = 0; r < 2; r++) {
            float v = s[r];
            v += __shfl_xor_sync(0xffffffffu, v, 1);
            v += __shfl_xor_sync(0xffffffffu, v, 2);
            if (t == 0)
                g_L[(i0 + w) * n + (j0 + g + 8 * r)] = v + b3d;
        }
    }
}

// ---------------------------------------------------------------------------
// Kernel 3: out[i,j] = (0.5*(L[i,j]+L[j,i]) + g1 - g0 > 0); flag near-margin.
// ---------------------------------------------------------------------------
__global__ void out_kernel(const float* __restrict__ u,
                           float* __restrict__ out,
                           int n)
{
    __shared__ float Lt[32][33];
    const int tx = threadIdx.x;
    const int ty = threadIdx.y;
    const int i0 = blockIdx.y * 32;
    const int j0 = blockIdx.x * 32;

#pragma unroll
    for (int r = 0; r < 4; r++) {
        const int jj = ty + 8 * r;
        Lt[jj][tx] = g_L[(j0 + jj) * n + (i0 + tx)];
    }
    __syncthreads();

#pragma unroll
    for (int r = 0; r < 4; r++) {
        const int ii = ty + 8 * r;
        const int i = i0 + ii;
        const int j = j0 + tx;
        const float lij = g_L[i * n + j];
        const float lji = Lt[tx][ii];
        const float lsym = 0.5f * (lij + lji);
        const float2 uv = ((const float2*)u)[i * n + j];
        const float g0 = -__logf(-__logf(uv.x + EPS_F) + EPS_F);
        const float g1 = -__logf(-__logf(uv.y + EPS_F) + EPS_F);
        const float z = lsym + g1 - g0;
        out[i * n + j] = (z > 0.0f) ? 1.0f : 0.0f;
        if (fabsf(z) < THRESH) {
            const int slot = atomicAdd(&g_fixcnt, 1);
            if (slot < FIXCAP) g_fixlist[slot] = (unsigned)(i << 10 | j);
        }
    }
}

// ---------------------------------------------------------------------------
// Kernel 4: exact fp32 recompute for flagged near-margin pairs.
// ---------------------------------------------------------------------------
__global__ void fixup_kernel(const float* __restrict__ W2,
                             const float* __restrict__ b2,
                             const float* __restrict__ W3,
                             const float* __restrict__ b3,
                             const float* __restrict__ u,
                             float* __restrict__ out,
                             int n)
{
    __shared__ float h1a[H1], h1b[H1], reda[H2], redb[H2];
    const int cnt = min(g_fixcnt, FIXCAP);
    const int c = threadIdx.x;   // 0..63

    for (int idx = blockIdx.x; idx < cnt; idx += gridDim.x) {
        const unsigned pk = g_fixlist[idx];
        const int i = pk >> 10, j = pk & 1023;

        for (int k = c; k < H1; k += 64) {
            h1a[k] = fmaxf(g_A[i * H1 + k] + g_B[j * H1 + k], 0.f);
            h1b[k] = fmaxf(g_A[j * H1 + k] + g_B[i * H1 + k], 0.f);
        }
        __syncthreads();

        float aa = b2[c], ab = b2[c];
        for (int k = 0; k < H1; k++) {
            const float wv = W2[k * H2 + c];
            aa = fmaf(h1a[k], wv, aa);
            ab = fmaf(h1b[k], wv, ab);
        }
        const float w3d = W3[c * 2 + 1] - W3[c * 2];
        reda[c] = fmaxf(aa, 0.f) * w3d;
        redb[c] = fmaxf(ab, 0.f) * w3d;
        __syncthreads();

        if (c == 0) {
            float La = 0.f, Lb = 0.f;
            for (int q = 0; q < H2; q++) { La += reda[q]; Lb += redb[q]; }
            const float b3d = b3[1] - b3[0];
            const float lsym = 0.5f * (La + Lb) + b3d;
            const float2 uv = ((const float2*)u)[i * n + j];
            const float g0 = -logf(-logf(uv.x + EPS_F) + EPS_F);
            const float g1 = -logf(-logf(uv.y + EPS_F) + EPS_F);
            out[i * n + j] = (lsym + g1 - g0 > 0.f) ? 1.0f : 0.0f;
        }
        __syncthreads();
    }
}

// ---------------------------------------------------------------------------
extern "C" void kernel_launch(void* const* d_in, const int* in_sizes, int n_in,
                              void* d_out, int out_size)
{
    const float* X  = (const float*)d_in[0];
    const float* W1 = (const float*)d_in[1];
    const float* b1 = (const float*)d_in[2];
    const float* W2 = (const float*)d_in[3];
    const float* b2 = (const float*)d_in[4];
    const float* W3 = (const float*)d_in[5];
    const float* b3 = (const float*)d_in[6];
    const float* u  = (const float*)d_in[7];
    float* out = (float*)d_out;

    const int n = in_sizes[0] / D;   // 1024

    static bool attr_set = false;
    if (!attr_set) {
        cudaFuncSetAttribute(pair_mma_kernel,
                             cudaFuncAttributeMaxDynamicSharedMemorySize,
                             SMEM_BYTES);
        attr_set = true;
    }

    ab_kernel<<<n / 2, 256>>>(X, W1, b1);
    w2prep_kernel<<<16, 256>>>(W2);

    dim3 g2(n / 64, n / 16);         // x: j-groups (4 tiles each), y: i-blocks
    pair_mma_kernel<<<g2, 512, SMEM_BYTES>>>(b2, W3, b3, n);

    dim3 b3d_(32, 8);
    dim3 g3(n / 32, n / 32);
    out_kernel<<<g3, b3d_>>>(u, out, n);

    fixup_kernel<<<256, 64>>>(W2, b2, W3, b3, u, out, n);
}

// round 15
// speedup vs baseline: 1.4148x; 1.4148x over previous
#include <cuda_runtime.h>
#include <cuda_bf16.h>
#include <cuda_fp16.h>
#include <cstdint>

#define D    64
#define H1   128
#define H2   64
#define NMAX 1024
#define EPS_F 1e-10f
#define THRESH 6e-3f
#define FIXCAP (1 << 20)

// Scratch (no allocations allowed)
__device__ float g_A[NMAX * H1];        // X @ W1[:D] + b1
__device__ float g_B[NMAX * H1];        // X @ W1[D:]
__device__ float g_L[NMAX * NMAX];      // logit diff per ordered pair
__device__ unsigned g_W2h[64 * 32 * 2]; // W2 fp16-hi packed B-frag words
__device__ unsigned int g_fixlist[FIXCAP];
__device__ int g_fixcnt;

// ---------------------------------------------------------------------------
// Kernel 1: A[i,k], B[i,k]. 2 rows per block, 256 threads (grid 512).
// ---------------------------------------------------------------------------
__global__ void ab_kernel(const float* __restrict__ X,
                          const float* __restrict__ W1,
                          const float* __restrict__ b1)
{
    __shared__ float xs[2][D];
    const int i0 = blockIdx.x * 2;
    const int tid = threadIdx.x;
    const int r = tid >> 7;              // row 0/1
    const int k = tid & 127;

    if (tid < 128) xs[tid >> 6][tid & 63] = X[i0 * D + tid];
    __syncthreads();

    float a = b1[k];
    float b = 0.0f;
#pragma unroll
    for (int d = 0; d < D; d++) {
        const float x = xs[r][d];
        a = fmaf(x, W1[d * H1 + k], a);
        b = fmaf(x, W1[(D + d) * H1 + k], b);
    }
    g_A[(i0 + r) * H1 + k] = a;
    g_B[(i0 + r) * H1 + k] = b;
}

// ---------------------------------------------------------------------------
// Kernel 1b: convert W2 to fp16 (hi part only; the dropped w_mid contributes
// ~2^-12 relative error, covered by the fixup threshold). Pack into
// B-fragment words: word[nn][ks*4+t][half] covers k = 16ks+2t(+1) (half=0)
// and k = 16ks+2t+8(+9) (half=1); lo f16 = even k, hi f16 = odd k.
// Also resets the fixup counter.
// ---------------------------------------------------------------------------
__global__ void w2prep_kernel(const float* __restrict__ W2)
{
    const int idx = blockIdx.x * 256 + threadIdx.x;   // 0..4095
    if (idx == 0) g_fixcnt = 0;
    const int nn = idx >> 6;       // output col n (0..63)
    const int kk = idx & 63;       // k-pair index (0..63)
    const float w0 = W2[(2 * kk) * H2 + nn];
    const float w1 = W2[(2 * kk + 1) * H2 + nn];
    const __half2 hw = __float22half2_rn(make_float2(w0, w1));
    const int ks = kk >> 3;
    const int gg = kk & 7;
    const int t = gg & 3;
    const int half = gg >> 2;     // 0 -> k base, 1 -> k+8
    g_W2h[(nn * 32 + ks * 4 + t) * 2 + half] = *(const unsigned*)&hw;
}

// ---------------------------------------------------------------------------
// Kernel 2: HMMA pair MLP (fp16 2-split). CTA = 256 thr (8 warps),
// tile = 16 i x 64 j (4 sub-tiles of 16x16). Warp w: pairs i = 2w,2w+1.
// h = relu(a+b) split into fp16 hi+mid (22-bit capture); W2 in fp16 hi.
// 2 MMA products per (nb, f): hi*whi + mid*whi. Error ~1e-4 << THRESH.
// ---------------------------------------------------------------------------
#define SB_STRIDE 136                    // floats; conflict-free B-frag loads
#define WQ_STRIDE 36                     // uint2; (4g+t) mod 16 distinct/phase
#define SM_BS_OFF (16 * 128)             // floats
#define SM_WQ_B   ((SM_BS_OFF + 16 * SB_STRIDE) * 4)   // byte offset, 8B-aligned
#define SM_B2_B   (SM_WQ_B + 64 * WQ_STRIDE * 8)
#define SM_W3_B   (SM_B2_B + 256)
#define SMEM_BYTES (SM_W3_B + 256)

__device__ __forceinline__ void mma_f16(float* c, const unsigned* a,
                                        unsigned b0, unsigned b1)
{
    asm("mma.sync.aligned.m16n8k16.row.col.f32.f16.f16.f32 "
        "{%0,%1,%2,%3}, {%4,%5,%6,%7}, {%8,%9}, {%0,%1,%2,%3};"
        : "+f"(c[0]), "+f"(c[1]), "+f"(c[2]), "+f"(c[3])
        : "r"(a[0]), "r"(a[1]), "r"(a[2]), "r"(a[3]), "r"(b0), "r"(b1));
}

__device__ __forceinline__ void hsplit16(float2 a, float2 b,
                                         unsigned& hi, unsigned& mid)
{
    const float h0 = fmaxf(a.x + b.x, 0.0f);
    const float h1 = fmaxf(a.y + b.y, 0.0f);
    const __half2 hh = __float22half2_rn(make_float2(h0, h1));
    hi = *(const unsigned*)&hh;
    const float2 back = __half22float2(hh);
    const __half2 mm = __float22half2_rn(make_float2(h0 - back.x, h1 - back.y));
    mid = *(const unsigned*)&mm;
}

__global__ __launch_bounds__(256, 2)
void pair_mma_kernel(const float* __restrict__ b2,
                     const float* __restrict__ W3,
                     const float* __restrict__ b3,
                     int n)
{
    extern __shared__ unsigned char smraw[];
    float* As  = (float*)smraw;                     // [16][128]
    float* Bs  = (float*)smraw + SM_BS_OFF;         // [16][136]
    uint2* W2q = (uint2*)(smraw + SM_WQ_B);         // [64][36]
    float* b2s = (float*)(smraw + SM_B2_B);         // [64]
    float* w3s = (float*)(smraw + SM_W3_B);         // [64]

    const int tid = threadIdx.x;
    const int w = tid >> 5;
    const int l = tid & 31;
    const int g = l >> 2;          // groupID 0..7
    const int t = l & 3;

    const int i0 = blockIdx.y * 16;

    // ---- stage As (16x128 fp32), W2 words (64x32 uint2), b2/w3 ----
    {
        const float4* srcA = (const float4*)g_A;
#pragma unroll
        for (int q = 0; q < 2; q++) {
            const int e = tid + q * 256;         // 0..511 float4s
            const int r = e >> 5, c4 = e & 31;
            *(float4*)&As[r * 128 + c4 * 4] = srcA[(i0 + r) * 32 + c4];
        }
        const uint2* srcW = (const uint2*)g_W2h;
#pragma unroll
        for (int q = 0; q < 8; q++) {
            const int e = tid + q * 256;         // 0..2047
            const int nn = e >> 5, c = e & 31;
            W2q[nn * WQ_STRIDE + c] = srcW[e];
        }
        if (tid < 64) {
            b2s[tid] = b2[tid];
            w3s[tid] = W3[tid * 2 + 1] - W3[tid * 2];
        }
    }
    const float b3d = __ldg(&b3[1]) - __ldg(&b3[0]);

    for (int tt = 0; tt < 4; tt++) {
        const int j0 = (blockIdx.x * 4 + tt) * 16;
        __syncthreads();   // protect Bs (and cover prologue on tt=0)
        {
            const float2* srcB = (const float2*)g_B;
#pragma unroll
            for (int q = 0; q < 4; q++) {
                const int e = tid + q * 256;     // 0..1023 float2s
                const int r = e >> 6, c2 = e & 63;
                *(float2*)&Bs[r * SB_STRIDE + c2 * 2] = srcB[(j0 + r) * 64 + c2];
            }
        }
        __syncthreads();

        float acc[2][8][4];
#pragma unroll
        for (int f = 0; f < 2; f++)
#pragma unroll
            for (int nb = 0; nb < 8; nb++)
#pragma unroll
                for (int c = 0; c < 4; c++) acc[f][nb][c] = 0.0f;

#pragma unroll
        for (int ks = 0; ks < 8; ks++) {
            const int k0 = ks * 16;
            const float2 blo_g  = *(const float2*)&Bs[g * SB_STRIDE + k0 + 2 * t];
            const float2 bhi_g  = *(const float2*)&Bs[g * SB_STRIDE + k0 + 2 * t + 8];
            const float2 blo_g8 = *(const float2*)&Bs[(g + 8) * SB_STRIDE + k0 + 2 * t];
            const float2 bhi_g8 = *(const float2*)&Bs[(g + 8) * SB_STRIDE + k0 + 2 * t + 8];

            unsigned ahi[2][4], amid[2][4];
#pragma unroll
            for (int f = 0; f < 2; f++) {
                const float2 alo = *(const float2*)&As[(2 * w + f) * 128 + k0 + 2 * t];
                const float2 ah2 = *(const float2*)&As[(2 * w + f) * 128 + k0 + 2 * t + 8];
                hsplit16(alo, blo_g,  ahi[f][0], amid[f][0]);  // row g
                hsplit16(alo, blo_g8, ahi[f][1], amid[f][1]);  // row g+8
                hsplit16(ah2, bhi_g,  ahi[f][2], amid[f][2]);  // row g,  k+8
                hsplit16(ah2, bhi_g8, ahi[f][3], amid[f][3]);  // row g+8,k+8
            }

            // Four 2-nb batches; product-major: 4 independent MMAs between
            // accumulator reuses.
#pragma unroll
            for (int qb = 0; qb < 4; qb++) {
                uint2 q[2];
#pragma unroll
                for (int nq = 0; nq < 2; nq++)
                    q[nq] = W2q[((qb * 2 + nq) * 8 + g) * WQ_STRIDE + ks * 4 + t];
#pragma unroll
                for (int nq = 0; nq < 2; nq++)             // hi * w_hi
#pragma unroll
                    for (int f = 0; f < 2; f++)
                        mma_f16(acc[f][qb * 2 + nq], ahi[f],  q[nq].x, q[nq].y);
#pragma unroll
                for (int nq = 0; nq < 2; nq++)             // mid * w_hi
#pragma unroll
                    for (int f = 0; f < 2; f++)
                        mma_f16(acc[f][qb * 2 + nq], amid[f], q[nq].x, q[nq].y);
            }
        }

        // ---- epilogue: +b2, relu, dot w3diff, reduce over 4 lanes ----
        float s[2][2] = {{0.f, 0.f}, {0.f, 0.f}};
#pragma unroll
        for (int nb = 0; nb < 8; nb++) {
            const float2 bb = *(const float2*)&b2s[nb * 8 + 2 * t];
            const float2 ww = *(const float2*)&w3s[nb * 8 + 2 * t];
#pragma unroll
            for (int f = 0; f < 2; f++) {
                s[f][0] += fmaxf(acc[f][nb][0] + bb.x, 0.f) * ww.x
                         + fmaxf(acc[f][nb][1] + bb.y, 0.f) * ww.y;
                s[f][1] += fmaxf(acc[f][nb][2] + bb.x, 0.f) * ww.x
                         + fmaxf(acc[f][nb][3] + bb.y, 0.f) * ww.y;
            }
        }
#pragma unroll
        for (int f = 0; f < 2; f++)
#pragma unroll
            for (int r = 0; r < 2; r++) {
                float v = s[f][r];
                v += __shfl_xor_sync(0xffffffffu, v, 1);
                v += __shfl_xor_sync(0xffffffffu, v, 2);
                if (t == 0)
                    g_L[(i0 + 2 * w + f) * n + (j0 + g + 8 * r)] = v + b3d;
            }
    }
}

// ---------------------------------------------------------------------------
// Kernel 3: out[i,j] = (0.5*(L[i,j]+L[j,i]) + g1 - g0 > 0); flag near-margin.
// ---------------------------------------------------------------------------
__global__ void out_kernel(const float* __restrict__ u,
                           float* __restrict__ out,
                           int n)
{
    __shared__ float Lt[32][33];
    const int tx = threadIdx.x;
    const int ty = threadIdx.y;
    const int i0 = blockIdx.y * 32;
    const int j0 = blockIdx.x * 32;

#pragma unroll
    for (int r = 0; r < 4; r++) {
        const int jj = ty + 8 * r;
        Lt[jj][tx] = g_L[(j0 + jj) * n + (i0 + tx)];
    }
    __syncthreads();

#pragma unroll
    for (int r = 0; r < 4; r++) {
        const int ii = ty + 8 * r;
        const int i = i0 + ii;
        const int j = j0 + tx;
        const float lij = g_L[i * n + j];
        const float lji = Lt[tx][ii];
        const float lsym = 0.5f * (lij + lji);
        const float2 uv = ((const float2*)u)[i * n + j];
        const float g0 = -__logf(-__logf(uv.x + EPS_F) + EPS_F);
        const float g1 = -__logf(-__logf(uv.y + EPS_F) + EPS_F);
        const float z = lsym + g1 - g0;
        out[i * n + j] = (z > 0.0f) ? 1.0f : 0.0f;
        if (fabsf(z) < THRESH) {
            const int slot = atomicAdd(&g_fixcnt, 1);
            if (slot < FIXCAP) g_fixlist[slot] = (unsigned)(i << 10 | j);
        }
    }
}

// ---------------------------------------------------------------------------
// Kernel 4: exact fp32 recompute for flagged near-margin pairs.
// ---------------------------------------------------------------------------
__global__ void fixup_kernel(const float* __restrict__ W2,
                             const float* __restrict__ b2,
                             const float* __restrict__ W3,
                             const float* __restrict__ b3,
                             const float* __restrict__ u,
                             float* __restrict__ out,
                             int n)
{
    __shared__ float h1a[H1], h1b[H1], reda[H2], redb[H2];
    const int cnt = min(g_fixcnt, FIXCAP);
    const int c = threadIdx.x;   // 0..63

    for (int idx = blockIdx.x; idx < cnt; idx += gridDim.x) {
        const unsigned pk = g_fixlist[idx];
        const int i = pk >> 10, j = pk & 1023;

        for (int k = c; k < H1; k += 64) {
            h1a[k] = fmaxf(g_A[i * H1 + k] + g_B[j * H1 + k], 0.f);
            h1b[k] = fmaxf(g_A[j * H1 + k] + g_B[i * H1 + k], 0.f);
        }
        __syncthreads();

        float aa = b2[c], ab = b2[c];
        for (int k = 0; k < H1; k++) {
            const float wv = W2[k * H2 + c];
            aa = fmaf(h1a[k], wv, aa);
            ab = fmaf(h1b[k], wv, ab);
        }
        const float w3d = W3[c * 2 + 1] - W3[c * 2];
        reda[c] = fmaxf(aa, 0.f) * w3d;
        redb[c] = fmaxf(ab, 0.f) * w3d;
        __syncthreads();

        if (c == 0) {
            float La = 0.f, Lb = 0.f;
            for (int q = 0; q < H2; q++) { La += reda[q]; Lb += redb[q]; }
            const float b3d = b3[1] - b3[0];
            const float lsym = 0.5f * (La + Lb) + b3d;
            const float2 uv = ((const float2*)u)[i * n + j];
            const float g0 = -logf(-logf(uv.x + EPS_F) + EPS_F);
            const float g1 = -logf(-logf(uv.y + EPS_F) + EPS_F);
            out[i * n + j] = (lsym + g1 - g0 > 0.f) ? 1.0f : 0.0f;
        }
        __syncthreads();
    }
}

// ---------------------------------------------------------------------------
extern "C" void kernel_launch(void* const* d_in, const int* in_sizes, int n_in,
                              void* d_out, int out_size)
{
    const float* X  = (const float*)d_in[0];
    const float* W1 = (const float*)d_in[1];
    const float* b1 = (const float*)d_in[2];
    const float* W2 = (const float*)d_in[3];
    const float* b2 = (const float*)d_in[4];
    const float* W3 = (const float*)d_in[5];
    const float* b3 = (const float*)d_in[6];
    const float* u  = (const float*)d_in[7];
    float* out = (float*)d_out;

    const int n = in_sizes[0] / D;   // 1024

    static bool attr_set = false;
    if (!attr_set) {
        cudaFuncSetAttribute(pair_mma_kernel,
                             cudaFuncAttributeMaxDynamicSharedMemorySize,
                             SMEM_BYTES);
        attr_set = true;
    }

    ab_kernel<<<n / 2, 256>>>(X, W1, b1);
    w2prep_kernel<<<16, 256>>>(W2);

    dim3 g2(n / 64, n / 16);         // x: j-groups (4 tiles each), y: i-blocks
    pair_mma_kernel<<<g2, 256, SMEM_BYTES>>>(b2, W3, b3, n);

    dim3 b3d_(32, 8);
    dim3 g3(n / 32, n / 32);
    out_kernel<<<g3, b3d_>>>(u, out, n);

    fixup_kernel<<<512, 64>>>(W2, b2, W3, b3, u, out, n);
}

// round 17
// speedup vs baseline: 1.9030x; 1.3450x over previous
#include <cuda_runtime.h>
#include <cuda_bf16.h>
#include <cuda_fp16.h>
#include <cstdint>

#define D    64
#define H1   128
#define H2   64
#define NMAX 1024
#define EPS_F 1e-10f
#define THRESH 8e-3f
#define FIXCAP (1 << 20)

// Scratch (no allocations allowed)
__device__ float g_A[NMAX * H1];        // X @ W1[:D] + b1
__device__ float g_B[NMAX * H1];        // X @ W1[D:]
__device__ float g_L[NMAX * NMAX];      // logit diff per ordered pair
__device__ unsigned g_W2h[64 * 32 * 2]; // W2 fp16 packed B-frag words
__device__ unsigned int g_fixlist[FIXCAP];
__device__ int g_fixcnt;

// ---------------------------------------------------------------------------
// Kernel 1: A[i,k], B[i,k]. 2 rows per block, 256 threads (grid 512).
// ---------------------------------------------------------------------------
__global__ void ab_kernel(const float* __restrict__ X,
                          const float* __restrict__ W1,
                          const float* __restrict__ b1)
{
    __shared__ float xs[2][D];
    const int i0 = blockIdx.x * 2;
    const int tid = threadIdx.x;
    const int r = tid >> 7;              // row 0/1
    const int k = tid & 127;

    if (tid < 128) xs[tid >> 6][tid & 63] = X[i0 * D + tid];
    __syncthreads();

    float a = b1[k];
    float b = 0.0f;
#pragma unroll
    for (int d = 0; d < D; d++) {
        const float x = xs[r][d];
        a = fmaf(x, W1[d * H1 + k], a);
        b = fmaf(x, W1[(D + d) * H1 + k], b);
    }
    g_A[(i0 + r) * H1 + k] = a;
    g_B[(i0 + r) * H1 + k] = b;
}

// ---------------------------------------------------------------------------
// Kernel 1b: convert W2 to fp16, pack into B-fragment words:
// word[nn][ks*4+t][half] covers k = 16ks+2t(+1) (half=0) and k = 16ks+2t+8(+9)
// (half=1); lo f16 = even k, hi f16 = odd k. Also resets the fixup counter.
// ---------------------------------------------------------------------------
__global__ void w2prep_kernel(const float* __restrict__ W2)
{
    const int idx = blockIdx.x * 256 + threadIdx.x;   // 0..4095
    if (idx == 0) g_fixcnt = 0;
    const int nn = idx >> 6;       // output col n (0..63)
    const int kk = idx & 63;       // k-pair index (0..63)
    const float w0 = W2[(2 * kk) * H2 + nn];
    const float w1 = W2[(2 * kk + 1) * H2 + nn];
    const __half2 hw = __float22half2_rn(make_float2(w0, w1));
    const int ks = kk >> 3;
    const int gg = kk & 7;
    const int t = gg & 3;
    const int half = gg >> 2;     // 0 -> k base, 1 -> k+8
    g_W2h[(nn * 32 + ks * 4 + t) * 2 + half] = *(const unsigned*)&hw;
}

// ---------------------------------------------------------------------------
// Kernel 2: HMMA pair MLP (single fp16 product). CTA = 256 thr (8 warps),
// tile = 16 i x 64 j (4 sub-tiles of 16x16). Warp w: pairs i = 2w,2w+1.
// h = relu(a+b) rounded once to fp16; W2 in fp16. One MMA product per
// (nb, f). Rounding error sigma_L ~ 4e-4 << THRESH=8e-3; near-margin pairs
// are recomputed exactly by fixup_kernel, so no output bit can flip.
// ---------------------------------------------------------------------------
#define SB_STRIDE 136                    // floats; conflict-free B-frag loads
#define WQ_STRIDE 36                     // uint2; (4g+t) mod 16 distinct/phase
#define SM_BS_OFF (16 * 128)             // floats
#define SM_WQ_B   ((SM_BS_OFF + 16 * SB_STRIDE) * 4)   // byte offset, 8B-aligned
#define SM_B2_B   (SM_WQ_B + 64 * WQ_STRIDE * 8)
#define SM_W3_B   (SM_B2_B + 256)
#define SMEM_BYTES (SM_W3_B + 256)

__device__ __forceinline__ void mma_f16(float* c, const unsigned* a,
                                        unsigned b0, unsigned b1)
{
    asm("mma.sync.aligned.m16n8k16.row.col.f32.f16.f16.f32 "
        "{%0,%1,%2,%3}, {%4,%5,%6,%7}, {%8,%9}, {%0,%1,%2,%3};"
        : "+f"(c[0]), "+f"(c[1]), "+f"(c[2]), "+f"(c[3])
        : "r"(a[0]), "r"(a[1]), "r"(a[2]), "r"(a[3]), "r"(b0), "r"(b1));
}

__device__ __forceinline__ unsigned hcvt(float2 a, float2 b)
{
    const __half2 hh = __float22half2_rn(
        make_float2(fmaxf(a.x + b.x, 0.0f), fmaxf(a.y + b.y, 0.0f)));
    return *(const unsigned*)&hh;
}

__global__ __launch_bounds__(256, 2)
void pair_mma_kernel(const float* __restrict__ b2,
                     const float* __restrict__ W3,
                     const float* __restrict__ b3,
                     int n)
{
    extern __shared__ unsigned char smraw[];
    float* As  = (float*)smraw;                     // [16][128]
    float* Bs  = (float*)smraw + SM_BS_OFF;         // [16][136]
    uint2* W2q = (uint2*)(smraw + SM_WQ_B);         // [64][36]
    float* b2s = (float*)(smraw + SM_B2_B);         // [64]
    float* w3s = (float*)(smraw + SM_W3_B);         // [64]

    const int tid = threadIdx.x;
    const int w = tid >> 5;
    const int l = tid & 31;
    const int g = l >> 2;          // groupID 0..7
    const int t = l & 3;

    const int i0 = blockIdx.y * 16;

    // ---- stage As (16x128 fp32), W2 words (64x32 uint2), b2/w3 ----
    {
        const float4* srcA = (const float4*)g_A;
#pragma unroll
        for (int q = 0; q < 2; q++) {
            const int e = tid + q * 256;         // 0..511 float4s
            const int r = e >> 5, c4 = e & 31;
            *(float4*)&As[r * 128 + c4 * 4] = srcA[(i0 + r) * 32 + c4];
        }
        const uint2* srcW = (const uint2*)g_W2h;
#pragma unroll
        for (int q = 0; q < 8; q++) {
            const int e = tid + q * 256;         // 0..2047
            const int nn = e >> 5, c = e & 31;
            W2q[nn * WQ_STRIDE + c] = srcW[e];
        }
        if (tid < 64) {
            b2s[tid] = b2[tid];
            w3s[tid] = W3[tid * 2 + 1] - W3[tid * 2];
        }
    }
    const float b3d = __ldg(&b3[1]) - __ldg(&b3[0]);

    for (int tt = 0; tt < 4; tt++) {
        const int j0 = (blockIdx.x * 4 + tt) * 16;
        __syncthreads();   // protect Bs (and cover prologue on tt=0)
        {
            const float2* srcB = (const float2*)g_B;
#pragma unroll
            for (int q = 0; q < 4; q++) {
                const int e = tid + q * 256;     // 0..1023 float2s
                const int r = e >> 6, c2 = e & 63;
                *(float2*)&Bs[r * SB_STRIDE + c2 * 2] = srcB[(j0 + r) * 64 + c2];
            }
        }
        __syncthreads();

        float acc[2][8][4];
#pragma unroll
        for (int f = 0; f < 2; f++)
#pragma unroll
            for (int nb = 0; nb < 8; nb++)
#pragma unroll
                for (int c = 0; c < 4; c++) acc[f][nb][c] = 0.0f;

#pragma unroll
        for (int ks = 0; ks < 8; ks++) {
            const int k0 = ks * 16;
            const float2 blo_g  = *(const float2*)&Bs[g * SB_STRIDE + k0 + 2 * t];
            const float2 bhi_g  = *(const float2*)&Bs[g * SB_STRIDE + k0 + 2 * t + 8];
            const float2 blo_g8 = *(const float2*)&Bs[(g + 8) * SB_STRIDE + k0 + 2 * t];
            const float2 bhi_g8 = *(const float2*)&Bs[(g + 8) * SB_STRIDE + k0 + 2 * t + 8];

            unsigned ahi[2][4];
#pragma unroll
            for (int f = 0; f < 2; f++) {
                const float2 alo = *(const float2*)&As[(2 * w + f) * 128 + k0 + 2 * t];
                const float2 ah2 = *(const float2*)&As[(2 * w + f) * 128 + k0 + 2 * t + 8];
                ahi[f][0] = hcvt(alo, blo_g);    // row g
                ahi[f][1] = hcvt(alo, blo_g8);   // row g+8
                ahi[f][2] = hcvt(ah2, bhi_g);    // row g,  k+8
                ahi[f][3] = hcvt(ah2, bhi_g8);   // row g+8,k+8
            }

            // Four 2-nb batches; 4 independent MMAs per batch, no acc reuse
            // inside a batch.
#pragma unroll
            for (int qb = 0; qb < 4; qb++) {
                uint2 q[2];
#pragma unroll
                for (int nq = 0; nq < 2; nq++)
                    q[nq] = W2q[((qb * 2 + nq) * 8 + g) * WQ_STRIDE + ks * 4 + t];
#pragma unroll
                for (int nq = 0; nq < 2; nq++)
#pragma unroll
                    for (int f = 0; f < 2; f++)
                        mma_f16(acc[f][qb * 2 + nq], ahi[f], q[nq].x, q[nq].y);
            }
        }

        // ---- epilogue: +b2, relu, dot w3diff, reduce over 4 lanes ----
        float s[2][2] = {{0.f, 0.f}, {0.f, 0.f}};
#pragma unroll
        for (int nb = 0; nb < 8; nb++) {
            const float2 bb = *(const float2*)&b2s[nb * 8 + 2 * t];
            const float2 ww = *(const float2*)&w3s[nb * 8 + 2 * t];
#pragma unroll
            for (int f = 0; f < 2; f++) {
                s[f][0] += fmaxf(acc[f][nb][0] + bb.x, 0.f) * ww.x
                         + fmaxf(acc[f][nb][1] + bb.y, 0.f) * ww.y;
                s[f][1] += fmaxf(acc[f][nb][2] + bb.x, 0.f) * ww.x
                         + fmaxf(acc[f][nb][3] + bb.y, 0.f) * ww.y;
            }
        }
#pragma unroll
        for (int f = 0; f < 2; f++)
#pragma unroll
            for (int r = 0; r < 2; r++) {
                float v = s[f][r];
                v += __shfl_xor_sync(0xffffffffu, v, 1);
                v += __shfl_xor_sync(0xffffffffu, v, 2);
                if (t == 0)
                    g_L[(i0 + 2 * w + f) * n + (j0 + g + 8 * r)] = v + b3d;
            }
    }
}

// ---------------------------------------------------------------------------
// Kernel 3: out[i,j] = (0.5*(L[i,j]+L[j,i]) + g1 - g0 > 0); flag near-margin.
// ---------------------------------------------------------------------------
__global__ void out_kernel(const float* __restrict__ u,
                           float* __restrict__ out,
                           int n)
{
    __shared__ float Lt[32][33];
    const int tx = threadIdx.x;
    const int ty = threadIdx.y;
    const int i0 = blockIdx.y * 32;
    const int j0 = blockIdx.x * 32;

#pragma unroll
    for (int r = 0; r < 4; r++) {
        const int jj = ty + 8 * r;
        Lt[jj][tx] = g_L[(j0 + jj) * n + (i0 + tx)];
    }
    __syncthreads();

#pragma unroll
    for (int r = 0; r < 4; r++) {
        const int ii = ty + 8 * r;
        const int i = i0 + ii;
        const int j = j0 + tx;
        const float lij = g_L[i * n + j];
        const float lji = Lt[tx][ii];
        const float lsym = 0.5f * (lij + lji);
        const float2 uv = ((const float2*)u)[i * n + j];
        const float g0 = -__logf(-__logf(uv.x + EPS_F) + EPS_F);
        const float g1 = -__logf(-__logf(uv.y + EPS_F) + EPS_F);
        const float z = lsym + g1 - g0;
        out[i * n + j] = (z > 0.0f) ? 1.0f : 0.0f;
        if (fabsf(z) < THRESH) {
            const int slot = atomicAdd(&g_fixcnt, 1);
            if (slot < FIXCAP) g_fixlist[slot] = (unsigned)(i << 10 | j);
        }
    }
}

// ---------------------------------------------------------------------------
// Kernel 4: exact fp32 recompute for flagged near-margin pairs.
// ---------------------------------------------------------------------------
__global__ void fixup_kernel(const float* __restrict__ W2,
                             const float* __restrict__ b2,
                             const float* __restrict__ W3,
                             const float* __restrict__ b3,
                             const float* __restrict__ u,
                             float* __restrict__ out,
                             int n)
{
    __shared__ float h1a[H1], h1b[H1], reda[H2], redb[H2];
    const int cnt = min(g_fixcnt, FIXCAP);
    const int c = threadIdx.x;   // 0..63

    for (int idx = blockIdx.x; idx < cnt; idx += gridDim.x) {
        const unsigned pk = g_fixlist[idx];
        const int i = pk >> 10, j = pk & 1023;

        for (int k = c; k < H1; k += 64) {
            h1a[k] = fmaxf(g_A[i * H1 + k] + g_B[j * H1 + k], 0.f);
            h1b[k] = fmaxf(g_A[j * H1 + k] + g_B[i * H1 + k], 0.f);
        }
        __syncthreads();

        float aa = b2[c], ab = b2[c];
        for (int k = 0; k < H1; k++) {
            const float wv = W2[k * H2 + c];
            aa = fmaf(h1a[k], wv, aa);
            ab = fmaf(h1b[k], wv, ab);
        }
        const float w3d = W3[c * 2 + 1] - W3[c * 2];
        reda[c] = fmaxf(aa, 0.f) * w3d;
        redb[c] = fmaxf(ab, 0.f) * w3d;
        __syncthreads();

        if (c == 0) {
            float La = 0.f, Lb = 0.f;
            for (int q = 0; q < H2; q++) { La += reda[q]; Lb += redb[q]; }
            const float b3d = b3[1] - b3[0];
            const float lsym = 0.5f * (La + Lb) + b3d;
            const float2 uv = ((const float2*)u)[i * n + j];
            const float g0 = -logf(-logf(uv.x + EPS_F) + EPS_F);
            const float g1 = -logf(-logf(uv.y + EPS_F) + EPS_F);
            out[i * n + j] = (lsym + g1 - g0 > 0.f) ? 1.0f : 0.0f;
        }
        __syncthreads();
    }
}

// ---------------------------------------------------------------------------
extern "C" void kernel_launch(void* const* d_in, const int* in_sizes, int n_in,
                              void* d_out, int out_size)
{
    const float* X  = (const float*)d_in[0];
    const float* W1 = (const float*)d_in[1];
    const float* b1 = (const float*)d_in[2];
    const float* W2 = (const float*)d_in[3];
    const float* b2 = (const float*)d_in[4];
    const float* W3 = (const float*)d_in[5];
    const float* b3 = (const float*)d_in[6];
    const float* u  = (const float*)d_in[7];
    float* out = (float*)d_out;

    const int n = in_sizes[0] / D;   // 1024

    static bool attr_set = false;
    if (!attr_set) {
        cudaFuncSetAttribute(pair_mma_kernel,
                             cudaFuncAttributeMaxDynamicSharedMemorySize,
                             SMEM_BYTES);
        attr_set = true;
    }

    ab_kernel<<<n / 2, 256>>>(X, W1, b1);
    w2prep_kernel<<<16, 256>>>(W2);

    dim3 g2(n / 64, n / 16);         // x: j-groups (4 tiles each), y: i-blocks
    pair_mma_kernel<<<g2, 256, SMEM_BYTES>>>(b2, W3, b3, n);

    dim3 b3d_(32, 8);
    dim3 g3(n / 32, n / 32);
    out_kernel<<<g3, b3d_>>>(u, out, n);

    fixup_kernel<<<512, 64>>>(W2, b2, W3, b3, u, out, n);
}